// round 6
// baseline (speedup 1.0000x reference)
#include <cuda_runtime.h>
#include <cuda_bf16.h>

// N=1, C=2, H=64, W=64, D=32, radius=(3,3,1), SIGMA_XY=5, SIGMA_IMG=0.1, WEIGHT=1
#define NH 64
#define NW 64
#define ND 32
#define NL (NH * NW * ND)      // 131072

#define TPB  256
#define NBLK (NL / TPB)        // 512 blocks; block = (h=2, w=4, d=32) slab

// smem tile: h 9 x w 10 x d 34 halo'd neighborhood, packed (s, y0)
#define TH 9
#define TW 10
#define TD 34
#define TSTRW TD               // 34
#define TSTRH (TW * TD)        // 340
#define TSIZE (TH * TW * TD)   // 3060
#define NROWS (TH * TW)        // 90

#define SENTINEL 1e19f
#define LOG2E 1.4426950408889634f

__device__ float    g_part[NBLK];
__device__ unsigned g_cnt = 0;   // last block resets to 0 (graph-replay safe)

__device__ __forceinline__ float ex2(float x) {   // guaranteed MUFU EX2
    float r;
    asm("ex2.approx.f32 %0, %1;" : "=f"(r) : "f"(x));
    return r;
}

__global__ __launch_bounds__(TPB) void k_all(const float* __restrict__ y,
                                             const float* __restrict__ s,
                                             const float* __restrict__ spacing,
                                             float* __restrict__ out) {
    __shared__ float2 tile[TSIZE];
    __shared__ float  warp_s[8];

    const int lane = threadIdx.x & 31;
    const int wrp  = threadIdx.x >> 5;          // 0..7

    // block -> slab origin
    const int hbase = (blockIdx.x >> 4) << 1;   // 0,2,...,62
    const int wbase = (blockIdx.x & 15) << 2;   // 0,4,...,60

    // ---- warp-row tile loader: all row math is warp-uniform ----
    // Row r covers tile[(th,tw, 0..33)], contiguous in smem and in gmem (d-axis).
    for (int r = wrp; r < NROWS; r += 8) {
        const int th = r / 10;                  // warp-uniform
        const int tw = r - th * 10;             // warp-uniform
        const int gh = hbase + th - 3;          // warp-uniform
        const int gw = wbase + tw - 3;          // warp-uniform
        const bool hw_ok = ((unsigned)gh < NH) & ((unsigned)gw < NW);   // uniform
        const int  tbase = r * TD;
        const int  gbase = (gh * NW + gw) * ND;

        // lane covers td = lane and (lanes 0,1) td = lane + 32
        {
            const int td = lane;
            const int gd = td - 1;
            float2 v = make_float2(SENTINEL, 0.0f);
            if (hw_ok & ((unsigned)gd < ND))
                v = make_float2(__ldg(s + gbase + gd), __ldg(y + gbase + gd));
            tile[tbase + td] = v;
        }
        if (lane < 2) {
            const int td = lane + 32;
            const int gd = td - 1;
            float2 v = make_float2(SENTINEL, 0.0f);
            if (hw_ok & ((unsigned)gd < ND))
                v = make_float2(__ldg(s + gbase + gd), __ldg(y + gbase + gd));
            tile[tbase + td] = v;
        }
    }
    __syncthreads();

    // thread -> voxel
    const int d  = threadIdx.x & 31;
    const int wl = (threadIdx.x >> 5) & 3;      // 0..3
    const int hl = threadIdx.x >> 7;            // 0..1
    const int w  = wbase + wl;
    const int h  = hbase + hl;
    const int tb = (hl + 3) * TSTRH + (wl + 3) * TSTRW + (d + 1);

    const float2 c0 = tile[tb];
    const float sp  = c0.x;
    const float y0p = c0.y;
    const float m   = 1.0f - 2.0f * y0p;        // 1 - dot = y0p + m*y0q  (C=2 softmax)

    const float sH = __ldg(spacing + 0);
    const float sW = __ldg(spacing + 1);
    const float sD = __ldg(spacing + 2);
    const float aH = sH * sH * (LOG2E / 50.0f);
    const float aW = sW * sW * (LOG2E / 50.0f);
    const float aD = sD * sD * (LOG2E / 50.0f);
    const float c2 = -50.0f * LOG2E;

    // Split sums: loss tap term = k*(y0p + m*y0q) = y0p*K + m*KY
    float K0 = 0.0f, K1 = 0.0f, KY0 = 0.0f, KY1 = 0.0f;
    int tap = 0;

    // Half-space offsets (73 of 146 non-center taps); each in-bounds pair
    // counted once, doubled below (k and (1-dot) are p<->q symmetric).
    // Sentinel halo drives ex2 -> exactly 0: branch-free immediate-offset LDS.
    #pragma unroll
    for (int dz = 0; dz <= 1; ++dz) {
        #pragma unroll
        for (int dw = -3; dw <= 3; ++dw) {
            #pragma unroll
            for (int dh = -3; dh <= 3; ++dh) {
                if (dz == 0 && (dw < 0 || (dw == 0 && dh <= 0))) continue;
                const float2 cq = tile[tb + dh * TSTRH + dw * TSTRW + dz];
                const float coff = -(aH * (float)(dh * dh)
                                   + aW * (float)(dw * dw)
                                   + aD * (float)(dz * dz));   // CSE'd constants
                const float ds = sp - cq.x;
                const float e2 = fmaf(c2 * ds, ds, coff);
                const float k  = ex2(e2);
                if (tap & 1) { K1 += k; KY1 = fmaf(k, cq.y, KY1); }
                else         { K0 += k; KY0 = fmaf(k, cq.y, KY0); }
                ++tap;
            }
        }
    }
    float acc = 2.0f * (y0p * (K0 + K1) + m * (KY0 + KY1));

    // OOB taps (zero-padded unfold): y-term 0; kernel value identical per
    // OOB offset: exp(-0.5*||f(p)||^2). Count analytically.
    const int cntH = min(h, 3) + min(NH - 1 - h, 3) + 1;
    const int cntW = min(w, 3) + min(NW - 1 - w, 3) + 1;
    const int cntD = min(d, 1) + min(ND - 1 - d, 1) + 1;
    const int noob = 147 - cntH * cntW * cntD;
    if (noob) {
        const float e = -(aH * (float)(h * h) + aW * (float)(w * w) + aD * (float)(d * d))
                        + c2 * sp * sp;
        acc = fmaf((float)noob, ex2(e), acc);
    }

    // ---- block reduction ----
    #pragma unroll
    for (int o = 16; o; o >>= 1) acc += __shfl_down_sync(0xffffffffu, acc, o);
    if (lane == 0) warp_s[wrp] = acc;
    __syncthreads();
    if (threadIdx.x == 0) {
        float b = 0.0f;
        #pragma unroll
        for (int j = 0; j < 8; ++j) b += warp_s[j];
        g_part[blockIdx.x] = b;
    }

    // ---- last-block final reduction ----
    __threadfence();
    __shared__ bool is_last;
    if (threadIdx.x == 0)
        is_last = (atomicAdd(&g_cnt, 1u) == NBLK - 1);
    __syncthreads();

    if (is_last) {
        float v = g_part[threadIdx.x] + g_part[threadIdx.x + 256];
        #pragma unroll
        for (int o = 16; o; o >>= 1) v += __shfl_down_sync(0xffffffffu, v, o);
        if (lane == 0) warp_s[wrp] = v;
        __syncthreads();
        if (threadIdx.x == 0) {
            float t = 0.0f;
            #pragma unroll
            for (int j = 0; j < 8; ++j) t += warp_s[j];
            out[0] = t * (1.0f / (float)NL);
            g_cnt = 0;                 // restore for next graph replay
        }
    }
}

extern "C" void kernel_launch(void* const* d_in, const int* in_sizes, int n_in,
                              void* d_out, int out_size) {
    const float* y       = (const float*)d_in[0];  // (1,2,64,64,32) softmax; ch 0 used
    const float* sample  = (const float*)d_in[1];  // (1,1,64,64,32)
    const float* spacing = (const float*)d_in[2];  // (3,1)
    k_all<<<NBLK, TPB>>>(y, sample, spacing, (float*)d_out);
}